// round 14
// baseline (speedup 1.0000x reference)
#include <cuda_runtime.h>
#include <cuda_bf16.h>

// SegEncodeLoss:
//   preds:   [32768, 19] float32
//   targets: [32, 1024, 1024] int32, labels in [0, 19)
//   grid_size = 32 (hardcoded)
//   out: scalar float = mean over (32768*19) of BCE(sigmoid(preds), presence)
//
// presence[n, c] = 1 if class c appears in the 32x32 tile n of targets.
// loss element  = softplus(x) - t*x   (stable BCE-with-logits identity)
//
// 4096 CTAs, 1 tile/warp, 8 CTAs/SM. Preds load hoisted above targets loads
// (one overlapped latency window). Per-warp shuffle-reduce replaced by a
// fire-and-forget shared-memory atomicAdd: the warp never waits on the
// reduction, so its memory duty cycle rises. Last-CTA-done final reduce.

#define NCLASS  19
#define NBLOCKS 32768
#define NCTA    (NBLOCKS / 8)   // 4096 CTAs, 8 warps each, 1 tile per warp

__device__ float    g_part[NCTA];
__device__ unsigned g_ctr = 0;   // wraps back to 0 every call via atomicInc

__global__ __launch_bounds__(256) void seg_loss_kernel(
    const float* __restrict__ preds,
    const int*   __restrict__ targets,
    float*       __restrict__ out)
{
    __shared__ float s_acc;
    __shared__ float ssum[8];
    __shared__ bool  s_last;

    if (threadIdx.x == 0) s_acc = 0.0f;
    __syncthreads();                     // publish zero before any atomics

    const int warp = (blockIdx.x * blockDim.x + threadIdx.x) >> 5;  // tile id
    const int lane = threadIdx.x & 31;

    // Prefetch this tile's logit FIRST — independent of the mask, so its
    // latency overlaps the targets loads instead of serializing after them.
    float x = 0.0f;
    if (lane < NCLASS)
        x = __ldg(&preds[warp * NCLASS + lane]);

    // tile id n = b*1024 + hb*32 + wb
    const int wb = warp & 31;
    const int hb = (warp >> 5) & 31;
    const int b  = warp >> 10;

    const int* base = targets + ((size_t)b << 20) + ((size_t)(hb << 5)) * 1024 + (wb << 5);

    // Each lane: int4 (4 labels) per row segment; 8 lanes cover the 128B row
    // chunk, 8 row-groups cover all 32 rows. All 8 loads independent (MLP=8).
    const int r0 = lane >> 3;
    const int c4 = (lane & 7) << 2;

    unsigned mask = 0u;
    #pragma unroll
    for (int it = 0; it < 8; ++it) {
        const int row = (it << 2) + r0;
        int4 v = __ldcs(reinterpret_cast<const int4*>(base + row * 1024 + c4));
        mask |= (1u << v.x) | (1u << v.y) | (1u << v.z) | (1u << v.w);
    }
    mask = __reduce_or_sync(0xffffffffu, mask);   // warp-wide presence mask

    if (lane < NCLASS) {
        const float sp = fmaxf(x, 0.0f) + log1pf(__expf(-fabsf(x)));  // softplus
        const float t  = (float)((mask >> lane) & 1u);
        atomicAdd(&s_acc, sp - t * x);   // fire-and-forget: no result wait
    }
    __syncthreads();                     // all contributions landed

    if (threadIdx.x == 0) {
        g_part[blockIdx.x] = s_acc;
        __threadfence();                              // partial visible first
        unsigned old = atomicInc(&g_ctr, NCTA - 1);   // wraps to 0 after NCTA-th
        s_last = (old == NCTA - 1);
    }
    __syncthreads();

    if (s_last) {
        __threadfence();   // acquire: see all g_part writes
        const int tid = threadIdx.x;
        float s = 0.0f;
        #pragma unroll
        for (int i = 0; i < NCTA / 256; ++i)    // 16 per thread, L2-resident
            s += g_part[tid + i * 256];

        #pragma unroll
        for (int o = 16; o > 0; o >>= 1)
            s += __shfl_down_sync(0xffffffffu, s, o);

        if (lane == 0) ssum[tid >> 5] = s;
        __syncthreads();
        if (tid == 0) {
            float tot = 0.0f;
            #pragma unroll
            for (int i = 0; i < 8; ++i) tot += ssum[i];
            out[0] = tot * (1.0f / (float)(NBLOCKS * NCLASS));
        }
    }
}

extern "C" void kernel_launch(void* const* d_in, const int* in_sizes, int n_in,
                              void* d_out, int out_size)
{
    const float* preds   = (const float*)d_in[0];
    const int*   targets = (const int*)d_in[1];
    float*       out     = (float*)d_out;

    seg_loss_kernel<<<NCTA, 256>>>(preds, targets, out);
}

// round 15
// speedup vs baseline: 2.7883x; 2.7883x over previous
#include <cuda_runtime.h>
#include <cuda_bf16.h>

// SegEncodeLoss:
//   preds:   [32768, 19] float32
//   targets: [32, 1024, 1024] int32, labels in [0, 19)
//   grid_size = 32 (hardcoded)
//   out: scalar float = mean over (32768*19) of BCE(sigmoid(preds), presence)
//
// presence[n, c] = 1 if class c appears in the 32x32 tile n of targets.
// loss element  = softplus(x) - t*x   (stable BCE-with-logits identity)
//
// 4096 CTAs, 1 tile/warp, 8 CTAs/SM. Preds load hoisted above targets loads.
// Per-warp tail minimized: each lane does ONE conflict-free spread atomicAdd
// into its own s_accs[lane] slot (fire-and-forget, 32 distinct banks — the
// R11 single-address version serialized and died). The 32->1 reduction runs
// once per CTA in warp 0. Last-CTA-done final reduce.

#define NCLASS  19
#define NBLOCKS 32768
#define NCTA    (NBLOCKS / 8)   // 4096 CTAs, 8 warps each, 1 tile per warp

__device__ float    g_part[NCTA];
__device__ unsigned g_ctr = 0;   // wraps back to 0 every call via atomicInc

__global__ __launch_bounds__(256) void seg_loss_kernel(
    const float* __restrict__ preds,
    const int*   __restrict__ targets,
    float*       __restrict__ out)
{
    __shared__ float s_accs[32];   // one slot per lane id -> distinct banks
    __shared__ float ssum[8];
    __shared__ bool  s_last;

    if (threadIdx.x < 32) s_accs[threadIdx.x] = 0.0f;
    __syncthreads();                      // publish zeros before any atomics

    const int warp = (blockIdx.x * blockDim.x + threadIdx.x) >> 5;  // tile id
    const int lane = threadIdx.x & 31;

    // Prefetch this tile's logit FIRST — independent of the mask, so its
    // latency overlaps the targets loads instead of serializing after them.
    float x = 0.0f;
    if (lane < NCLASS)
        x = __ldg(&preds[warp * NCLASS + lane]);

    // tile id n = b*1024 + hb*32 + wb
    const int wb = warp & 31;
    const int hb = (warp >> 5) & 31;
    const int b  = warp >> 10;

    const int* base = targets + ((size_t)b << 20) + ((size_t)(hb << 5)) * 1024 + (wb << 5);

    // Each lane: int4 (4 labels) per row segment; 8 lanes cover the 128B row
    // chunk, 8 row-groups cover all 32 rows. All 8 loads independent (MLP=8).
    const int r0 = lane >> 3;
    const int c4 = (lane & 7) << 2;

    unsigned mask = 0u;
    #pragma unroll
    for (int it = 0; it < 8; ++it) {
        const int row = (it << 2) + r0;
        int4 v = __ldcs(reinterpret_cast<const int4*>(base + row * 1024 + c4));
        mask |= (1u << v.x) | (1u << v.y) | (1u << v.z) | (1u << v.w);
    }
    mask = __reduce_or_sync(0xffffffffu, mask);   // warp-wide presence mask

    if (lane < NCLASS) {
        const float sp = fmaxf(x, 0.0f) + log1pf(__expf(-fabsf(x)));  // softplus
        const float t  = (float)((mask >> lane) & 1u);
        // Conflict-free (per-lane slot) fire-and-forget accumulate.
        atomicAdd(&s_accs[lane], sp - t * x);
    }
    __syncthreads();                      // all contributions landed

    // Warp 0: reduce the 32 slots, publish partial, bump the counter.
    if (threadIdx.x < 32) {
        float s = s_accs[lane];
        #pragma unroll
        for (int o = 16; o > 0; o >>= 1)
            s += __shfl_down_sync(0xffffffffu, s, o);
        if (lane == 0) {
            g_part[blockIdx.x] = s;
            __threadfence();                              // partial visible first
            unsigned old = atomicInc(&g_ctr, NCTA - 1);   // wraps to 0 after NCTA-th
            s_last = (old == NCTA - 1);
        }
    }
    __syncthreads();

    if (s_last) {
        __threadfence();   // acquire: see all g_part writes
        const int tid = threadIdx.x;
        float s = 0.0f;
        #pragma unroll
        for (int i = 0; i < NCTA / 256; ++i)    // 16 per thread, L2-resident
            s += g_part[tid + i * 256];

        #pragma unroll
        for (int o = 16; o > 0; o >>= 1)
            s += __shfl_down_sync(0xffffffffu, s, o);

        if (lane == 0) ssum[tid >> 5] = s;
        __syncthreads();
        if (tid == 0) {
            float tot = 0.0f;
            #pragma unroll
            for (int i = 0; i < 8; ++i) tot += ssum[i];
            out[0] = tot * (1.0f / (float)(NBLOCKS * NCLASS));
        }
    }
}

extern "C" void kernel_launch(void* const* d_in, const int* in_sizes, int n_in,
                              void* d_out, int out_size)
{
    const float* preds   = (const float*)d_in[0];
    const int*   targets = (const int*)d_in[1];
    float*       out     = (float*)d_out;

    seg_loss_kernel<<<NCTA, 256>>>(preds, targets, out);
}

// round 17
// speedup vs baseline: 3.0408x; 1.0906x over previous
#include <cuda_runtime.h>
#include <cuda_bf16.h>

// SegEncodeLoss:
//   preds:   [32768, 19] float32
//   targets: [32, 1024, 1024] int32, labels in [0, 19)
//   grid_size = 32 (hardcoded)
//   out: scalar float = mean over (32768*19) of BCE(sigmoid(preds), presence)
//
// presence[n, c] = 1 if class c appears in the 32x32 tile n of targets.
// loss element  = softplus(x) - t*x   (stable BCE-with-logits identity)
//
// SINGLE-WAVE persistent layout: 1024 CTAs x 256 thr, __launch_bounds__(256,7)
// -> 148*7 = 1036 concurrent slots >= 1024 CTAs: one wave, no transitions,
// no CTA churn. Each warp processes exactly 4 tiles through a NON-unrolled
// loop (keeps regs ~33, unlike the R7 full-unroll that hit 40 regs / 2 ragged
// waves). Loads stay in flight continuously across iterations.

#define NCLASS  19
#define NBLOCKS 32768
#define NCTA    1024
#define NWARPS  (NCTA * 8)          // 8192 warps
#define TPW     (NBLOCKS / NWARPS)  // 4 tiles per warp, exact

__device__ float    g_part[NCTA];
__device__ unsigned g_ctr = 0;   // wraps back to 0 every call via atomicInc

__global__ __launch_bounds__(256, 7) void seg_loss_kernel(
    const float* __restrict__ preds,
    const int*   __restrict__ targets,
    float*       __restrict__ out)
{
    const int warp = (blockIdx.x * blockDim.x + threadIdx.x) >> 5;  // 0..8191
    const int lane = threadIdx.x & 31;

    // Per-lane fixed intra-tile offsets: int4 (4 labels) per row segment;
    // 8 lanes cover a 128B row chunk, 8 row-groups cover 32 rows.
    const int r0 = lane >> 3;
    const int c4 = (lane & 7) << 2;

    float contrib = 0.0f;

    #pragma unroll 1
    for (int t = 0; t < TPW; ++t) {
        const int tile = warp + t * NWARPS;   // stride 8192 -> distinct batches

        // Prefetch this tile's logit first; overlaps the targets loads.
        float x = 0.0f;
        if (lane < NCLASS)
            x = __ldg(&preds[tile * NCLASS + lane]);

        const int wb = tile & 31;
        const int hb = (tile >> 5) & 31;
        const int b  = tile >> 10;
        const int* base = targets + ((size_t)b << 20)
                        + ((size_t)(hb << 5)) * 1024 + (wb << 5);

        unsigned mask = 0u;
        #pragma unroll
        for (int it = 0; it < 8; ++it) {
            const int row = (it << 2) + r0;
            int4 v = __ldcs(reinterpret_cast<const int4*>(base + row * 1024 + c4));
            mask |= (1u << v.x) | (1u << v.y) | (1u << v.z) | (1u << v.w);
        }
        mask = __reduce_or_sync(0xffffffffu, mask);   // warp-wide presence

        if (lane < NCLASS) {
            const float sp = fmaxf(x, 0.0f) + log1pf(__expf(-fabsf(x)));
            const float tt = (float)((mask >> lane) & 1u);
            contrib += sp - tt * x;
        }
    }

    // warp sum (once per warp, after all 4 tiles)
    #pragma unroll
    for (int o = 16; o > 0; o >>= 1)
        contrib += __shfl_down_sync(0xffffffffu, contrib, o);

    __shared__ float ssum[8];
    __shared__ bool  s_last;
    if (lane == 0) ssum[threadIdx.x >> 5] = contrib;
    __syncthreads();

    if (threadIdx.x == 0) {
        float s = 0.0f;
        #pragma unroll
        for (int i = 0; i < 8; ++i) s += ssum[i];
        g_part[blockIdx.x] = s;
        __threadfence();                              // partial visible first
        unsigned old = atomicInc(&g_ctr, NCTA - 1);   // wraps to 0 after NCTA-th
        s_last = (old == NCTA - 1);
    }
    __syncthreads();

    if (s_last) {
        __threadfence();   // acquire: see all g_part writes
        const int tid = threadIdx.x;
        float s = 0.0f;
        #pragma unroll
        for (int i = 0; i < NCTA / 256; ++i)    // 4 per thread, L2-resident
            s += g_part[tid + i * 256];

        #pragma unroll
        for (int o = 16; o > 0; o >>= 1)
            s += __shfl_down_sync(0xffffffffu, s, o);

        if (lane == 0) ssum[tid >> 5] = s;
        __syncthreads();
        if (tid == 0) {
            float tot = 0.0f;
            #pragma unroll
            for (int i = 0; i < 8; ++i) tot += ssum[i];
            out[0] = tot * (1.0f / (float)(NBLOCKS * NCLASS));
        }
    }
}

extern "C" void kernel_launch(void* const* d_in, const int* in_sizes, int n_in,
                              void* d_out, int out_size)
{
    const float* preds   = (const float*)d_in[0];
    const int*   targets = (const int*)d_in[1];
    float*       out     = (float*)d_out;

    seg_loss_kernel<<<NCTA, 256>>>(preds, targets, out);
}